// round 7
// baseline (speedup 1.0000x reference)
#include <cuda_runtime.h>
#include <cuda_bf16.h>

// MIoU (buggy-faithful): answer = popcount(presence mask of classes 1..20 in y_pred) / 21.
// y_true irrelevant. Presence is monotone: a single warp sampling 1024 elements
// (32 lanes x 8 int4, one MLP=8 latency window) sees every class with prob 1-3e-21.
// Zero barriers, zero smem, one warp, one graph node. Fallback scans the full array
// for arbitrary-input correctness (never taken on this input).
// [R7: final form — minimal params; workload is launch-floor bound (noise band 4.8-6.9us).]

#define FULL_MASK 0x001FFFFEu  // bits 1..20

__global__ void __launch_bounds__(32) k_miou(const int4* __restrict__ p, unsigned n4,
                                             unsigned ntail, float* __restrict__ out) {
    const unsigned lane = threadIdx.x;
    unsigned m = 0u;

    // Fast path: 8 independent vector loads per lane (4 KB contiguous = 1024 elems),
    // all overlapped in one L2/DRAM latency window.
    const unsigned FAST = 8u * 32u;
    if (FAST <= n4) {
#pragma unroll
        for (unsigned j = 0; j < 8u; ++j) {
            int4 v = __ldcg(&p[j * 32u + lane]);  // values in [0,20]
            m |= (1u << v.x) | (1u << v.y) | (1u << v.z) | (1u << v.w);
        }
    }

    unsigned wm = __reduce_or_sync(0xffffffffu, m);

    if ((wm & FULL_MASK) != FULL_MASK) {
        // Cold fallback (prob ~3e-21 on this data): warp grid-strides the remainder,
        // re-checking completeness periodically. Produces the exact answer regardless.
        unsigned i = (FAST <= n4 ? FAST : 0u) + lane;
        for (; i < n4; i += 32u) {
            int4 v = __ldcg(&p[i]);
            m |= (1u << v.x) | (1u << v.y) | (1u << v.z) | (1u << v.w);
            if ((i & 1023u) >= 992u) {
                wm = __reduce_or_sync(0xffffffffu, m);
                if ((wm & FULL_MASK) == FULL_MASK) break;
            }
        }
        // Scalar tail (n % 4 elements; zero for this shape, kept for generality).
        const int* y = (const int*)p;
        for (unsigned j = n4 * 4u + lane; j < n4 * 4u + ntail; j += 32u)
            m |= 1u << __ldcg(&y[j]);
        wm = __reduce_or_sync(0xffffffffu, m);
    }

    if (lane == 0)
        out[0] = (float)__popc(wm & FULL_MASK) / 21.0f;
}

extern "C" void kernel_launch(void* const* d_in, const int* in_sizes, int n_in,
                              void* d_out, int out_size) {
    const int* y_pred   = (const int*)d_in[0];
    const unsigned n    = (unsigned)in_sizes[0];
    const unsigned n4   = n / 4u;
    const unsigned tail = n - n4 * 4u;

    k_miou<<<1, 32>>>((const int4*)y_pred, n4, tail, (float*)d_out);
}

// round 8
// speedup vs baseline: 1.5211x; 1.5211x over previous
#include <cuda_runtime.h>
#include <cuda_bf16.h>

// MIoU (buggy-faithful): answer = popcount(presence mask of classes 1..20 in y_pred) / 21.
// y_true irrelevant. Presence is monotone: a single warp sampling 1024 elements
// (32 lanes x 8 int4, all overlapped in one L2 latency window) sees every class with
// prob 1-3e-21 on 21-class uniform data. Zero barriers, zero smem, one warp, one graph
// node. Cold fallback scans the full array for arbitrary-input correctness (never taken).
//
// [R8 FINAL] Structural floor reached: 1 node / 1 warp / 1 load window / 1 REDUX / 1 STG.
// Wall-time spread 4.8-6.9us is harness replay + DVFS noise (identical source measured
// 4.86, 6.50, 6.91 across rounds; ncu floor ~3.9us even for an empty kernel).

#define FULL_MASK 0x001FFFFEu  // bits 1..20

__global__ void __launch_bounds__(32) k_miou(const int4* __restrict__ p, unsigned n4,
                                             unsigned ntail, float* __restrict__ out) {
    const unsigned lane = threadIdx.x;
    const unsigned FAST = 8u * 32u;  // int4s in fast path (1024 elements)
    unsigned m = 0u;

    if (n4 >= FAST) {
        // Hot path: straight-line, 8 independent LDG.128 (4 KB contiguous).
#pragma unroll
        for (unsigned j = 0; j < 8u; ++j) {
            int4 v = __ldcg(&p[j * 32u + lane]);  // values in [0,20]
            m |= (1u << v.x) | (1u << v.y) | (1u << v.z) | (1u << v.w);
        }
        unsigned wm = __reduce_or_sync(0xffffffffu, m);
        if ((wm & FULL_MASK) == FULL_MASK) {
            if (lane == 0) out[0] = (float)__popc(wm & FULL_MASK) / 21.0f;
            return;
        }
    }

    // Cold path (prob ~3e-21 on this data; exact for arbitrary inputs):
    // warp grid-strides the whole array with periodic completeness checks.
    unsigned wm;
    for (unsigned i = (n4 >= FAST ? FAST : 0u) + lane; i < n4; i += 32u) {
        int4 v = __ldcg(&p[i]);
        m |= (1u << v.x) | (1u << v.y) | (1u << v.z) | (1u << v.w);
        if ((i & 1023u) >= 992u) {
            wm = __reduce_or_sync(0xffffffffu, m);
            if ((wm & FULL_MASK) == FULL_MASK) break;
        }
    }
    // Scalar tail (n % 4 elements; zero for this shape, kept for generality).
    const int* y = (const int*)p;
    for (unsigned j = n4 * 4u + lane; j < n4 * 4u + ntail; j += 32u)
        m |= 1u << __ldcg(&y[j]);
    wm = __reduce_or_sync(0xffffffffu, m);

    if (lane == 0)
        out[0] = (float)__popc(wm & FULL_MASK) / 21.0f;
}

extern "C" void kernel_launch(void* const* d_in, const int* in_sizes, int n_in,
                              void* d_out, int out_size) {
    const int* y_pred   = (const int*)d_in[0];
    const unsigned n    = (unsigned)in_sizes[0];
    const unsigned n4   = n / 4u;
    const unsigned tail = n - n4 * 4u;

    k_miou<<<1, 32>>>((const int4*)y_pred, n4, tail, (float*)d_out);
}